// round 2
// baseline (speedup 1.0000x reference)
#include <cuda_runtime.h>

#define NB 32
#define NC 3
#define NH 256
#define NW 256
#define KS 29
#define PADK 14
#define HID 32
#define TY 16
#define TX 16
#define HW (NH*NW)
#define NPIX (NB*NC*NH*NW)

// scratch (static device allocations are allowed)
__device__ float g_z1[NB*NC*HW];
__device__ float g_z2[NB*NC*HW];
__device__ float g_k1[NB][KS];
__device__ float g_tn[NB];
__device__ float g_partials[NB*(NH/TY)*(NW/TX)];   // 8192

// ---------------------------------------------------------------------------
// 1) per-batch gaussian taps + normalized time
// ---------------------------------------------------------------------------
__global__ void prep_kernel(const int* __restrict__ t,
                            const float* __restrict__ sched) {
    int b = threadIdx.x;
    if (b >= NB) return;
    int ti = t[b];
    float sigma = sched[ti];
    float vals[KS];
    float s = 0.f;
#pragma unroll
    for (int k = 0; k < KS; k++) {
        float xg = (float)(k - PADK) / sigma;
        float v = expf(-0.5f * xg * xg);
        vals[k] = v;
        s += v;
    }
    float inv = 1.f / s;
#pragma unroll
    for (int k = 0; k < KS; k++) g_k1[b][k] = vals[k] * inv;
    g_tn[b] = (float)ti * (1.0f / 1000.0f);
}

// ---------------------------------------------------------------------------
// 2) vertical blur (reflect pad), coalesced along x
// ---------------------------------------------------------------------------
__global__ void blurV_kernel(const float* __restrict__ x) {
    __shared__ float kk[KS];
    int bc = blockIdx.y;          // 0..95  (b*3+c)
    int y  = blockIdx.x;          // 0..255
    int xx = threadIdx.x;         // 0..255
    int b  = bc / NC;
    if (xx < KS) kk[xx] = g_k1[b][xx];
    __syncthreads();
    const float* src = x + (size_t)bc * HW;
    float acc = 0.f;
#pragma unroll
    for (int k = 0; k < KS; k++) {
        int yy = y - PADK + k;
        yy = (yy < 0) ? -yy : ((yy >= NH) ? (2*NH - 2 - yy) : yy);
        acc = fmaf(kk[k], src[yy*NW + xx], acc);
    }
    g_z1[(size_t)bc*HW + y*NW + xx] = acc;
}

// ---------------------------------------------------------------------------
// 3) horizontal blur (reflect pad), row staged in smem
// ---------------------------------------------------------------------------
__global__ void blurH_kernel() {
    __shared__ float kk[KS];
    __shared__ float row[NW];
    int bc = blockIdx.y;
    int y  = blockIdx.x;
    int xx = threadIdx.x;
    int b  = bc / NC;
    if (xx < KS) kk[xx] = g_k1[b][xx];
    row[xx] = g_z1[(size_t)bc*HW + y*NW + xx];
    __syncthreads();
    float acc = 0.f;
#pragma unroll
    for (int k = 0; k < KS; k++) {
        int xi = xx - PADK + k;
        xi = (xi < 0) ? -xi : ((xi >= NW) ? (2*NW - 2 - xi) : xi);
        acc = fmaf(kk[k], row[xi], acc);
    }
    g_z2[(size_t)bc*HW + y*NW + xx] = acc;
}

// ---------------------------------------------------------------------------
// 4) fused conv1(3->32,3x3,SAME,zero pad) + bias + t-embed + relu
//          + conv2(32->3,3x3,SAME) + bias + squared-error + block reduce
//    One block = one 16x16 output tile of one batch sample.
//    Dynamic smem layout (floats):
//      zs   [3*20*20 = 1200]   z tile with halo 2   (reused as ws2v later)
//      hs   [32*18*18 = 10368] hidden tile with halo 1
//      ws1  [864]              W1
//      misc [72]               b1(32) tw(32) warp-sums(8)
// ---------------------------------------------------------------------------
__global__ void conv_loss_kernel(const float* __restrict__ x,
                                 const float* __restrict__ W1,
                                 const float* __restrict__ b1,
                                 const float* __restrict__ tw,
                                 const float* __restrict__ W2,
                                 const float* __restrict__ b2) {
    extern __shared__ float sm[];
    float* zs   = sm;             // 1200
    float* hs   = sm + 1200;      // 10368
    float* ws1  = sm + 11568;     // 864
    float* misc = sm + 12432;     // 72
    float* ws2v = zs;             // reuse after conv1 (1152 <= 1200)

    int tid = threadIdx.x;                 // 256 threads
    int bx = blockIdx.x, by = blockIdx.y, b = blockIdx.z;
    int x0 = bx*TX, y0 = by*TY;

    for (int i = tid; i < HID*NC*9; i += 256) ws1[i] = W1[i];
    if (tid < HID) { misc[tid] = b1[tid]; misc[HID + tid] = tw[tid]; }
    float tn = g_tn[b];

    // z tile with halo 2 (zero pad outside image)
    const float* zsrc = g_z2 + (size_t)b*NC*HW;
    for (int i = tid; i < NC*20*20; i += 256) {
        int ch = i / 400;
        int rr = (i / 20) % 20;
        int cc = i % 20;
        int gy = y0 - 2 + rr, gx = x0 - 2 + cc;
        float v = 0.f;
        if ((unsigned)gy < NH && (unsigned)gx < NW)
            v = zsrc[ch*HW + gy*NW + gx];
        zs[i] = v;
    }
    __syncthreads();

    // conv1 over 18x18 hidden region; each active thread does 2 positions so
    // every W1 smem load feeds 2 FMAs.
    if (tid < 162) {
        int p0 = tid, p1 = tid + 162;
        int r0 = p0/18, c0 = p0%18;
        int r1 = p1/18, c1 = p1%18;
        float za[27], zb[27];
#pragma unroll
        for (int ch = 0; ch < 3; ch++)
#pragma unroll
            for (int ky = 0; ky < 3; ky++)
#pragma unroll
                for (int kx = 0; kx < 3; kx++) {
                    za[ch*9+ky*3+kx] = zs[ch*400 + (r0+ky)*20 + (c0+kx)];
                    zb[ch*9+ky*3+kx] = zs[ch*400 + (r1+ky)*20 + (c1+kx)];
                }
        int gy0 = y0 - 1 + r0, gx0 = x0 - 1 + c0;
        int gy1 = y0 - 1 + r1, gx1 = x0 - 1 + c1;
        bool in0 = (unsigned)gy0 < NH && (unsigned)gx0 < NW;
        bool in1 = (unsigned)gy1 < NH && (unsigned)gx1 < NW;
#pragma unroll 4
        for (int o = 0; o < HID; o++) {
            float base = misc[o] + tn * misc[HID + o];
            float a0 = base, a1 = base;
#pragma unroll
            for (int j = 0; j < 27; j++) {
                float wv = ws1[o*27 + j];
                a0 = fmaf(wv, za[j], a0);
                a1 = fmaf(wv, zb[j], a1);
            }
            // h outside the image must be exactly 0 (conv2 zero padding)
            hs[o*324 + p0] = in0 ? fmaxf(a0, 0.f) : 0.f;
            hs[o*324 + p1] = in1 ? fmaxf(a1, 0.f) : 0.f;
        }
    }
    __syncthreads();

    // pack W2 transposed [o][9][co] into float4 slots (reusing zs region)
    for (int i = tid; i < HID*9; i += 256) {
        ws2v[i*4+0] = W2[i];          // co=0
        ws2v[i*4+1] = W2[288 + i];    // co=1
        ws2v[i*4+2] = W2[576 + i];    // co=2
        ws2v[i*4+3] = 0.f;
    }
    __syncthreads();

    // conv2: one output pixel per thread, all 3 output channels together
    int r = tid >> 4, c = tid & 15;
    float a0 = b2[0], a1 = b2[1], a2 = b2[2];
    const float4* w2f = (const float4*)ws2v;
#pragma unroll 4
    for (int o = 0; o < HID; o++) {
        const float* hb = hs + o*324 + r*18 + c;
#pragma unroll
        for (int ky = 0; ky < 3; ky++)
#pragma unroll
            for (int kx = 0; kx < 3; kx++) {
                float hv = hb[ky*18 + kx];
                float4 w = w2f[o*9 + ky*3 + kx];
                a0 = fmaf(hv, w.x, a0);
                a1 = fmaf(hv, w.y, a1);
                a2 = fmaf(hv, w.z, a2);
            }
    }

    int gy = y0 + r, gx = x0 + c;
    const float* xb = x + (size_t)b*NC*HW + gy*NW + gx;
    float d0 = xb[0]      - a0;
    float d1 = xb[HW]     - a1;
    float d2 = xb[2*HW]   - a2;
    float e = d0*d0 + d1*d1 + d2*d2;

    // block reduce
#pragma unroll
    for (int off = 16; off; off >>= 1) e += __shfl_down_sync(0xffffffffu, e, off);
    float* wsum = misc + 64;
    if ((tid & 31) == 0) wsum[tid >> 5] = e;
    __syncthreads();
    if (tid < 8) {
        float v = wsum[tid];
#pragma unroll
        for (int off = 4; off; off >>= 1) v += __shfl_down_sync(0xffu, v, off);
        if (tid == 0)
            g_partials[(b*16 + by)*16 + bx] = v;
    }
}

// ---------------------------------------------------------------------------
// 5) final reduce (double) -> mean
// ---------------------------------------------------------------------------
__global__ void finalize_kernel(float* __restrict__ out) {
    __shared__ double sh[256];
    int tid = threadIdx.x;
    double acc = 0.0;
    for (int i = tid; i < NB*256; i += 256) acc += (double)g_partials[i];
    sh[tid] = acc;
    __syncthreads();
    for (int s = 128; s; s >>= 1) {
        if (tid < s) sh[tid] += sh[tid + s];
        __syncthreads();
    }
    if (tid == 0) out[0] = (float)(sh[0] / (double)NPIX);
}

// ---------------------------------------------------------------------------
extern "C" void kernel_launch(void* const* d_in, const int* in_sizes, int n_in,
                              void* d_out, int out_size) {
    const float* x     = (const float*)d_in[0];   // [32,3,256,256]
    const int*   t     = (const int*)  d_in[1];   // [32]
    const float* W1    = (const float*)d_in[2];   // [32,3,3,3]
    const float* b1    = (const float*)d_in[3];   // [32]
    const float* tw    = (const float*)d_in[4];   // [32]
    const float* W2    = (const float*)d_in[5];   // [3,32,3,3]
    const float* b2    = (const float*)d_in[6];   // [3]
    const float* sched = (const float*)d_in[7];   // [1000]

    prep_kernel<<<1, NB>>>(t, sched);
    blurV_kernel<<<dim3(NH, NB*NC), NW>>>(x);
    blurH_kernel<<<dim3(NH, NB*NC), NW>>>();

    const int smem_bytes = 12504 * (int)sizeof(float);   // 50016 B
    cudaFuncSetAttribute(conv_loss_kernel,
                         cudaFuncAttributeMaxDynamicSharedMemorySize, smem_bytes);
    conv_loss_kernel<<<dim3(NW/TX, NH/TY, NB), 256, smem_bytes>>>(x, W1, b1, tw, W2, b2);

    finalize_kernel<<<1, 256>>>((float*)d_out);
}

// round 4
// speedup vs baseline: 1.5480x; 1.5480x over previous
#include <cuda_runtime.h>

#define NB 32
#define NC 3
#define NH 256
#define NW 256
#define KS 29
#define PADK 14
#define HID 32
#define TY 16
#define TX 16
#define HW (NH*NW)
#define NPIX (NB*NC*NH*NW)

__device__ float g_z2[NB*NC*HW];
__device__ float g_k1[NB][KS];
__device__ float g_tn[NB];
__device__ float g_partials[NB*(NH/TY)*(NW/TX)];

// ---------------- packed f32x2 helpers (sm_103a) ----------------
typedef unsigned long long u64t;

__device__ __forceinline__ u64t pk2(float a, float b) {
    u64t r; asm("mov.b64 %0, {%1,%2};" : "=l"(r) : "f"(a), "f"(b)); return r;
}
__device__ __forceinline__ void upk2(u64t v, float& a, float& b) {
    asm("mov.b64 {%0,%1}, %2;" : "=f"(a), "=f"(b) : "l"(v));
}
__device__ __forceinline__ u64t fma2(u64t a, u64t b, u64t c) {
    u64t d; asm("fma.rn.f32x2 %0, %1, %2, %3;" : "=l"(d) : "l"(a), "l"(b), "l"(c));
    return d;
}
__device__ __forceinline__ void lds2u64(unsigned s, u64t& a, u64t& b) {
    asm volatile("ld.shared.v2.u64 {%0,%1}, [%2];" : "=l"(a), "=l"(b) : "r"(s));
}
__device__ __forceinline__ void sts4f(unsigned s, float a, float b, float c, float d) {
    asm volatile("st.shared.v4.f32 [%0], {%1,%2,%3,%4};" :: "r"(s), "f"(a), "f"(b), "f"(c), "f"(d));
}

// ---------------------------------------------------------------------------
// 1) per-batch gaussian taps + normalized time
// ---------------------------------------------------------------------------
__global__ void prep_kernel(const int* __restrict__ t,
                            const float* __restrict__ sched) {
    int b = threadIdx.x;
    if (b >= NB) return;
    int ti = t[b];
    float sigma = sched[ti];
    float vals[KS];
    float s = 0.f;
#pragma unroll
    for (int k = 0; k < KS; k++) {
        float xg = (float)(k - PADK) / sigma;
        float v = expf(-0.5f * xg * xg);
        vals[k] = v;
        s += v;
    }
    float inv = 1.f / s;
#pragma unroll
    for (int k = 0; k < KS; k++) g_k1[b][k] = vals[k] * inv;
    g_tn[b] = (float)ti * (1.0f / 1000.0f);
}

// ---------------------------------------------------------------------------
// 2) fused separable blur (reflect). One block = 32-row strip of one (b,c).
//    smem: xin[60][256] -> vt[32][257] -> hout (reuses xin, stride 257)
//    Sliding-window 8-accumulator scheme: 144 LDS / 928 FMA per pass.
// ---------------------------------------------------------------------------
#define BXIN 0
#define BVT  15360
#define BKK  23584
#define BLUR_SMEM ((23584 + 32) * 4)

__global__ __launch_bounds__(256, 2)
void blur_kernel(const float* __restrict__ x) {
    extern __shared__ float s[];
    float* xin = s + BXIN;     // 60*256
    float* vt  = s + BVT;      // 32*257
    float* kk  = s + BKK;      // 29
    float* hout = s + BXIN;    // reuse, stride 257

    int bc = blockIdx.y;
    int b  = bc / NC;
    int y0 = blockIdx.x * 32;
    int tid = threadIdx.x;
    if (tid < KS) kk[tid] = g_k1[b][tid];

    const float* src = x + (size_t)bc * HW;
    int c4 = (tid & 63) * 4;
    for (int i = tid >> 6; i < 60; i += 4) {
        int gy = y0 - PADK + i;
        gy = gy < 0 ? -gy : (gy > NH-1 ? 2*(NH-1) - gy : gy);
        *(float4*)&xin[i*256 + c4] = *(const float4*)&src[gy*NW + c4];
    }
    __syncthreads();

    float kr[KS];
#pragma unroll
    for (int k = 0; k < KS; k++) kr[k] = kk[k];

    // vertical: thread = column tid, 4 chunks of 8 output rows
#pragma unroll 1
    for (int ch = 0; ch < 4; ch++) {
        int cr = ch * 8;
        float acc[8] = {0,0,0,0,0,0,0,0};
#pragma unroll
        for (int i = 0; i < 36; i++) {
            float v = xin[(cr + i)*256 + tid];
#pragma unroll
            for (int a = 0; a < 8; a++) {
                int k = i - a;
                if (k >= 0 && k < KS) acc[a] = fmaf(kr[k], v, acc[a]);
            }
        }
#pragma unroll
        for (int a = 0; a < 8; a++) vt[(cr + a)*257 + tid] = acc[a];
    }
    __syncthreads();

    // horizontal: thread = (row tid&31, col-chunk tid>>5), 4 chunks of 8 cols
    int rr = tid & 31, c0 = (tid >> 5) * 32;
#pragma unroll 1
    for (int ch = 0; ch < 4; ch++) {
        int cs = c0 + ch * 8;
        float acc[8] = {0,0,0,0,0,0,0,0};
#pragma unroll
        for (int i = 0; i < 36; i++) {
            int xi = cs - PADK + i;
            xi = xi < 0 ? -xi : xi;
            xi = xi > NW-1 ? 2*(NW-1) - xi : xi;
            float v = vt[rr*257 + xi];
#pragma unroll
            for (int a = 0; a < 8; a++) {
                int k = i - a;
                if (k >= 0 && k < KS) acc[a] = fmaf(kr[k], v, acc[a]);
            }
        }
#pragma unroll
        for (int a = 0; a < 8; a++) hout[rr*257 + cs + a] = acc[a];
    }
    __syncthreads();

    float* dst = g_z2 + (size_t)bc * HW + (size_t)y0 * NW;
#pragma unroll 1
    for (int r2 = 0; r2 < 32; r2++)
        dst[r2*NW + tid] = hout[r2*257 + tid];
}

// ---------------------------------------------------------------------------
// 3) fused conv1 + relu + conv2 + squared-error + reduce (f32x2 packed)
//    smem floats: hs[324*36]=11664 @0 | zs[1200] @11664 | ws1d[1792] @12864
//                 ws2[864] @14656 | misc[72] @15520  -> 15616 floats
// ---------------------------------------------------------------------------
#define CHS   0
#define CZS   11664
#define CWS1  12864
#define CWS2  14656
#define CMISC 15520
#define CONV_SMEM (15616 * 4)

__global__ __launch_bounds__(256, 3)
void conv_loss_kernel(const float* __restrict__ x,
                      const float* __restrict__ W1,
                      const float* __restrict__ b1,
                      const float* __restrict__ tw,
                      const float* __restrict__ W2,
                      const float* __restrict__ b2) {
    extern __shared__ float sm[];
    float* hs   = sm + CHS;
    float* zs   = sm + CZS;
    float* ws1  = sm + CWS1;
    float* ws2  = sm + CWS2;
    float* misc = sm + CMISC;

    unsigned smem_u = (unsigned)__cvta_generic_to_shared(sm);
    int tid = threadIdx.x;
    int bx = blockIdx.x, by = blockIdx.y, b = blockIdx.z;
    int x0 = bx*TX, y0 = by*TY;

    // --- load phase ---
    for (int i = tid; i < HID*NC*9; i += 256) {
        int o = i / 27, j = i % 27;
        float v = W1[i];
        ws1[o*56 + 2*j] = v;
        ws1[o*56 + 2*j + 1] = v;
    }
    if (tid < HID) { ws1[tid*56 + 54] = 0.f; ws1[tid*56 + 55] = 0.f; }
    for (int i = tid; i < NC*HID*9; i += 256) {
        int co = i / 288, rem = i % 288, o = rem / 9, tap = rem % 9;
        ws2[(co*9 + tap)*32 + o] = W2[i];
    }
    if (tid < HID) { misc[tid] = b1[tid]; misc[HID + tid] = tw[tid]; }
    float tn = g_tn[b];

    const float* zsrc = g_z2 + (size_t)b*NC*HW;
    for (int i = tid; i < NC*20*20; i += 256) {
        int ch = i / 400, rr = (i / 20) % 20, cc = i % 20;
        int gy = y0 - 2 + rr, gx = x0 - 2 + cc;
        float v = 0.f;
        if ((unsigned)gy < NH && (unsigned)gx < NW)
            v = zsrc[ch*HW + gy*NW + gx];
        zs[i] = v;
    }
    __syncthreads();

    // --- conv1: 162 threads x 2 positions packed in f32x2 ---
    if (tid < 162) {
        int p0 = tid, p1 = tid + 162;
        int r0 = p0/18, c0 = p0%18, r1 = p1/18, c1 = p1%18;
        u64t pz[28];
#pragma unroll
        for (int ch = 0; ch < 3; ch++)
#pragma unroll
            for (int ky = 0; ky < 3; ky++)
#pragma unroll
                for (int kx = 0; kx < 3; kx++) {
                    int j = ch*9 + ky*3 + kx;
                    pz[j] = pk2(zs[ch*400 + (r0+ky)*20 + (c0+kx)],
                                zs[ch*400 + (r1+ky)*20 + (c1+kx)]);
                }
        pz[27] = 0ULL;
        int gy0 = y0-1+r0, gx0 = x0-1+c0, gy1 = y0-1+r1, gx1 = x0-1+c1;
        bool in0 = (unsigned)gy0 < NH && (unsigned)gx0 < NW;
        bool in1 = (unsigned)gy1 < NH && (unsigned)gx1 < NW;

        unsigned ws1_s = smem_u + CWS1*4;
        unsigned hs0 = smem_u + (unsigned)(p0*36)*4;
        unsigned hs1 = smem_u + (unsigned)(p1*36)*4;
#pragma unroll 1
        for (int og = 0; og < 8; og++) {
            float s0[4], s1[4];
#pragma unroll
            for (int oi = 0; oi < 4; oi++) {
                int o = og*4 + oi;
                float base = fmaf(tn, misc[HID + o], misc[o]);
                u64t acc = pk2(base, base);
                unsigned wa = ws1_s + (unsigned)o*224;
#pragma unroll
                for (int j2 = 0; j2 < 14; j2++) {
                    u64t w0, w1;
                    lds2u64(wa + j2*16, w0, w1);
                    acc = fma2(w0, pz[2*j2], acc);
                    acc = fma2(w1, pz[2*j2+1], acc);
                }
                float lo, hi; upk2(acc, lo, hi);
                s0[oi] = in0 ? fmaxf(lo, 0.f) : 0.f;
                s1[oi] = in1 ? fmaxf(hi, 0.f) : 0.f;
            }
            sts4f(hs0 + og*16, s0[0], s0[1], s0[2], s0[3]);
            sts4f(hs1 + og*16, s1[0], s1[1], s1[2], s1[3]);
        }
    }
    __syncthreads();

    // --- conv2: 128 threads, 2 vertically-adjacent pixels, o packed in f32x2 ---
    float e = 0.f;
    if (tid < 128) {
        int c = tid & 15, r = (tid >> 4) * 2;   // pixels (r,c),(r+1,c)
        u64t a0[3] = {0,0,0}, a1[3] = {0,0,0};
        unsigned hbase = smem_u + (unsigned)((r*18 + c)*36)*4;
        unsigned wbase = smem_u + CWS2*4;
#pragma unroll 1
        for (int og = 0; og < 8; og++) {
#pragma unroll
            for (int kx = 0; kx < 3; kx++) {
                u64t h[4][2];
#pragma unroll
                for (int u = 0; u < 4; u++)
                    lds2u64(hbase + (unsigned)((u*18 + kx)*36)*4 + og*16,
                            h[u][0], h[u][1]);
#pragma unroll
                for (int co = 0; co < 3; co++)
#pragma unroll
                    for (int ky = 0; ky < 3; ky++) {
                        u64t w0, w1;
                        lds2u64(wbase + (unsigned)(((co*9 + ky*3 + kx)*8 + og))*16,
                                w0, w1);
                        a0[co] = fma2(w0, h[ky][0],   a0[co]);
                        a0[co] = fma2(w1, h[ky][1],   a0[co]);
                        a1[co] = fma2(w0, h[ky+1][0], a1[co]);
                        a1[co] = fma2(w1, h[ky+1][1], a1[co]);
                    }
            }
        }
        int gy = y0 + r, gx = x0 + c;
        const float* xb = x + (size_t)b*NC*HW + gy*NW + gx;
#pragma unroll
        for (int co = 0; co < 3; co++) {
            float lo, hi;
            upk2(a0[co], lo, hi); float pr0 = lo + hi + b2[co];
            upk2(a1[co], lo, hi); float pr1 = lo + hi + b2[co];
            float d0 = xb[co*HW]      - pr0;
            float d1 = xb[co*HW + NW] - pr1;
            e += d0*d0 + d1*d1;
        }
    }

    // block reduce (all 256 threads; e==0 for tid>=128)
#pragma unroll
    for (int off = 16; off; off >>= 1) e += __shfl_down_sync(0xffffffffu, e, off);
    float* wsum = misc + 64;
    if ((tid & 31) == 0) wsum[tid >> 5] = e;
    __syncthreads();
    if (tid < 8) {
        float v = wsum[tid];
#pragma unroll
        for (int off = 4; off; off >>= 1) v += __shfl_down_sync(0xffu, v, off);
        if (tid == 0)
            g_partials[(b*16 + by)*16 + bx] = v;
    }
}

// ---------------------------------------------------------------------------
// 4) final reduce (double) -> mean
// ---------------------------------------------------------------------------
__global__ void finalize_kernel(float* __restrict__ out) {
    __shared__ double sh[256];
    int tid = threadIdx.x;
    double acc = 0.0;
    for (int i = tid; i < NB*256; i += 256) acc += (double)g_partials[i];
    sh[tid] = acc;
    __syncthreads();
    for (int s = 128; s; s >>= 1) {
        if (tid < s) sh[tid] += sh[tid + s];
        __syncthreads();
    }
    if (tid == 0) out[0] = (float)(sh[0] / (double)NPIX);
}

// ---------------------------------------------------------------------------
extern "C" void kernel_launch(void* const* d_in, const int* in_sizes, int n_in,
                              void* d_out, int out_size) {
    const float* x     = (const float*)d_in[0];
    const int*   t     = (const int*)  d_in[1];
    const float* W1    = (const float*)d_in[2];
    const float* b1    = (const float*)d_in[3];
    const float* tw    = (const float*)d_in[4];
    const float* W2    = (const float*)d_in[5];
    const float* b2    = (const float*)d_in[6];
    const float* sched = (const float*)d_in[7];

    prep_kernel<<<1, NB>>>(t, sched);

    cudaFuncSetAttribute(blur_kernel,
                         cudaFuncAttributeMaxDynamicSharedMemorySize, BLUR_SMEM);
    blur_kernel<<<dim3(NH/32, NB*NC), 256, BLUR_SMEM>>>(x);

    cudaFuncSetAttribute(conv_loss_kernel,
                         cudaFuncAttributeMaxDynamicSharedMemorySize, CONV_SMEM);
    conv_loss_kernel<<<dim3(NW/TX, NH/TY, NB), 256, CONV_SMEM>>>(x, W1, b1, tw, W2, b2);

    finalize_kernel<<<1, 256>>>((float*)d_out);
}